// round 6
// baseline (speedup 1.0000x reference)
#include <cuda_runtime.h>
#include <cstdint>

// Problem dims (fixed by dataset)
#define NQ1   10001
#define NQA1  20001
#define MSZ   64
#define KD    128
#define VD    256
#define VM    256
#define FD    128
#define BB    512
#define SS    512

typedef unsigned long long ull;

// ---------------------------------------------------------------------------
// f32x2 packed-math + cp.async helpers
// ---------------------------------------------------------------------------
__device__ __forceinline__ ull pk2(float a, float b) {
    ull r; asm("mov.b64 %0, {%1, %2};" : "=l"(r) : "f"(a), "f"(b)); return r;
}
__device__ __forceinline__ void upk2(ull p, float& a, float& b) {
    asm("mov.b64 {%0, %1}, %2;" : "=f"(a), "=f"(b) : "l"(p));
}
__device__ __forceinline__ ull fma2(ull a, ull b, ull c) {
    ull d; asm("fma.rn.f32x2 %0, %1, %2, %3;" : "=l"(d) : "l"(a), "l"(b), "l"(c)); return d;
}
__device__ __forceinline__ uint32_t s2u(const void* p) {
    uint32_t a;
    asm("{ .reg .u64 t; cvta.to.shared.u64 t, %1; cvt.u32.u64 %0, t; }" : "=r"(a) : "l"(p));
    return a;
}
__device__ __forceinline__ void cpa4(uint32_t s, const void* g) {
    asm volatile("cp.async.ca.shared.global [%0], [%1], 4;" :: "r"(s), "l"(g));
}
#define CPA_COMMIT() asm volatile("cp.async.commit_group;" ::: "memory")
#define CPA_WAIT0()  asm volatile("cp.async.wait_group 0;"  ::: "memory")

// ---------------------------------------------------------------------------
// Scratch tables
// ---------------------------------------------------------------------------
__device__ float g_wtab [NQ1  * MSZ];
__device__ float g_fktab[NQ1  * FD ];
__device__ float g_etab [NQA1 * VM ];
__device__ float g_atab [NQA1 * VM ];
__device__ float g_WeT  [VD * VM];
__device__ float g_WaT  [VD * VM];

// ---------------------------------------------------------------------------
// Transpose We/Wa (256x256) into [j][u] layout
// ---------------------------------------------------------------------------
__global__ void transpose_we_wa(const float* __restrict__ We,
                                const float* __restrict__ Wa)
{
    __shared__ float tile[32][33];
    const float* src = blockIdx.z ? Wa : We;
    float* dst = blockIdx.z ? g_WaT : g_WeT;
    const int bx = blockIdx.x * 32;
    const int by = blockIdx.y * 32;
    #pragma unroll
    for (int k = 0; k < 4; k++)
        tile[threadIdx.y + k * 8][threadIdx.x] =
            src[(by + threadIdx.y + k * 8) * VD + bx + threadIdx.x];
    __syncthreads();
    #pragma unroll
    for (int k = 0; k < 4; k++)
        dst[(bx + threadIdx.y + k * 8) * VM + by + threadIdx.x] =
            tile[threadIdx.x][threadIdx.y + k * 8];
}

// ---------------------------------------------------------------------------
// Kernel A: per-q tables (32 indices/block, coalesced + conflict-free)
// ---------------------------------------------------------------------------
#define WTI 32
#define WFK_SMEM ((WTI*KD + MSZ*132 + FD*132 + WTI*MSZ) * 4)

__global__ void __launch_bounds__(256)
build_wfk_kernel(const float* __restrict__ k_emb, const float* __restrict__ Mk,
                 const float* __restrict__ Wf,    const float* __restrict__ bf)
{
    extern __shared__ float sm[];
    float* k_s   = sm;
    float* Mk_s  = sm + WTI * KD;
    float* Wfk_s = Mk_s + MSZ * 132;
    float* sc_s  = Wfk_s + FD * 132;

    const int tid  = threadIdx.x;
    const int base = blockIdx.x * WTI;

    for (int idx = tid; idx < WTI * KD; idx += 256) {
        const int i = idx >> 7, j = idx & 127;
        const int gi = min(base + i, NQ1 - 1);
        k_s[i * KD + j] = k_emb[gi * KD + j];
    }
    for (int idx = tid; idx < MSZ * KD; idx += 256) {
        const int m = idx >> 7, j = idx & 127;
        Mk_s[m * 132 + j] = Mk[idx];
    }
    for (int idx = tid; idx < FD * KD; idx += 256) {
        const int ff = idx >> 7, j = idx & 127;
        Wfk_s[ff * 132 + j] = Wf[ff * (KD + VM) + VM + j];
    }
    __syncthreads();

    {
        const int m = tid & 63, ig = tid >> 6;
        float acc[8];
        #pragma unroll
        for (int ii = 0; ii < 8; ii++) acc[ii] = 0.f;
        #pragma unroll 4
        for (int j4 = 0; j4 < KD / 4; j4++) {
            const float4 mk = *reinterpret_cast<const float4*>(Mk_s + m * 132 + j4 * 4);
            #pragma unroll
            for (int ii = 0; ii < 8; ii++) {
                const float4 kv = *reinterpret_cast<const float4*>(k_s + (ig * 8 + ii) * KD + j4 * 4);
                acc[ii] = fmaf(mk.x, kv.x, fmaf(mk.y, kv.y, fmaf(mk.z, kv.z, fmaf(mk.w, kv.w, acc[ii]))));
            }
        }
        #pragma unroll
        for (int ii = 0; ii < 8; ii++) sc_s[(ig * 8 + ii) * MSZ + m] = acc[ii];
    }
    __syncthreads();

    {
        const int lane = tid & 31, w = tid >> 5;
        #pragma unroll
        for (int rep = 0; rep < 4; rep++) {
            const int i = w + rep * 8;
            const float sa = sc_s[i * MSZ + lane];
            const float sb = sc_s[i * MSZ + 32 + lane];
            float mx = fmaxf(sa, sb);
            #pragma unroll
            for (int o = 16; o > 0; o >>= 1) mx = fmaxf(mx, __shfl_xor_sync(0xffffffffu, mx, o));
            const float ea = expf(sa - mx), eb = expf(sb - mx);
            float s = ea + eb;
            #pragma unroll
            for (int o = 16; o > 0; o >>= 1) s += __shfl_xor_sync(0xffffffffu, s, o);
            const float inv = 1.f / s;
            const int gi = base + i;
            if (gi < NQ1) {
                g_wtab[gi * MSZ + lane]      = ea * inv;
                g_wtab[gi * MSZ + 32 + lane] = eb * inv;
            }
        }
    }

    {
        const int ff = tid & 127, h = tid >> 7;
        float fa[16];
        #pragma unroll
        for (int ii = 0; ii < 16; ii++) fa[ii] = 0.f;
        #pragma unroll 2
        for (int j4 = 0; j4 < KD / 4; j4++) {
            const float4 wv = *reinterpret_cast<const float4*>(Wfk_s + ff * 132 + j4 * 4);
            #pragma unroll
            for (int ii = 0; ii < 16; ii++) {
                const float4 kv = *reinterpret_cast<const float4*>(k_s + (h * 16 + ii) * KD + j4 * 4);
                fa[ii] = fmaf(wv.x, kv.x, fmaf(wv.y, kv.y, fmaf(wv.z, kv.z, fmaf(wv.w, kv.w, fa[ii]))));
            }
        }
        const float bff = bf[ff];
        #pragma unroll
        for (int ii = 0; ii < 16; ii++) {
            const int gi = base + h * 16 + ii;
            if (gi < NQ1) g_fktab[gi * FD + ff] = fa[ii] + bff;
        }
    }
}

// ---------------------------------------------------------------------------
// Kernel B: per-qa tables from transposed weights
// ---------------------------------------------------------------------------
#define TI 32
__global__ void __launch_bounds__(256)
build_ea_kernel(const float* __restrict__ v_emb,
                const float* __restrict__ be, const float* __restrict__ ba)
{
    __shared__ float4 v_s[TI * (VD / 4)];
    const int tid  = threadIdx.x;
    const int base = blockIdx.x * TI;

    for (int idx = tid; idx < TI * (VD / 4); idx += 256) {
        const int i = idx >> 6, j4 = idx & 63;
        const int gi = min(base + i, NQA1 - 1);
        v_s[i * (VD / 4) + j4] = reinterpret_cast<const float4*>(v_emb)[gi * (VD / 4) + j4];
    }
    __syncthreads();

    const int u = tid;
    float acce[TI], acca[TI];
    #pragma unroll
    for (int i = 0; i < TI; i++) { acce[i] = 0.f; acca[i] = 0.f; }

    #pragma unroll 1
    for (int j4 = 0; j4 < VD / 4; j4++) {
        const int j = j4 * 4;
        const float we0 = g_WeT[(j + 0) * VM + u];
        const float we1 = g_WeT[(j + 1) * VM + u];
        const float we2 = g_WeT[(j + 2) * VM + u];
        const float we3 = g_WeT[(j + 3) * VM + u];
        const float wa0 = g_WaT[(j + 0) * VM + u];
        const float wa1 = g_WaT[(j + 1) * VM + u];
        const float wa2 = g_WaT[(j + 2) * VM + u];
        const float wa3 = g_WaT[(j + 3) * VM + u];
        #pragma unroll
        for (int i = 0; i < TI; i++) {
            const float4 v = v_s[i * (VD / 4) + j4];
            acce[i] = fmaf(we0, v.x, fmaf(we1, v.y, fmaf(we2, v.z, fmaf(we3, v.w, acce[i]))));
            acca[i] = fmaf(wa0, v.x, fmaf(wa1, v.y, fmaf(wa2, v.z, fmaf(wa3, v.w, acca[i]))));
        }
    }

    const float bei = be[u], bai = ba[u];
    #pragma unroll
    for (int i = 0; i < TI; i++) {
        const int gi = base + i;
        if (gi < NQA1) {
            g_etab[gi * VM + u] = 1.f / (1.f + expf(-(acce[i] + bei)));
            g_atab[gi * VM + u] = tanhf(acca[i] + bai);
        }
    }
}

// ---------------------------------------------------------------------------
// Main kernel: 512 threads (16 warps, 4/SMSP), 4 steps/span, <=128 regs.
//   Phase A: thread (u = tid&255, mh = tid>>8): mv2[16] regs, half the m-range
//   Phase B: thread (f = tid&127, g = tid>>7):  wfr[32] regs, u-quarter
//   span s: cp.async prefetch -> A x4 + E(s-1) -> bar
//           fold r halves + out-store(s-1)     -> bar
//           B x4 -> cp.wait -> bar
// ---------------------------------------------------------------------------
#define TSP 4
#define NSP (SS / TSP)
#define STG 258

// smem layout (floats)
#define O_E     0                               // [2][TSP][256]
#define O_A     (O_E  + 2 * TSP * VM)
#define O_WW    (O_A  + 2 * TSP * VM)           // [2][TSP][64]
#define O_FK    (O_WW + 2 * TSP * MSZ)          // [2][TSP][128]
#define O_RP    (O_FK + 2 * TSP * FD)           // [TSP][512] partials
#define O_RF    (O_RP + TSP * 512)              // [TSP][256] folded r
#define O_FP    (O_RF + TSP * VM)               // [TSP][512] f partials
#define O_RED   (O_FP + TSP * 512)              // [TSP*4]
#define O_Q     (O_RED + TSP * 4)               // [512] int
#define O_QA    (O_Q + SS)
#define O_STAGE (O_QA + SS)                     // 32*258
#define MAIN_SMEM ((O_STAGE + 32 * STG) * 4)

__global__ void __launch_bounds__(512, 1)
dkvmn_main_kernel(const int* __restrict__ q,  const int* __restrict__ qa,
                  const float* __restrict__ Wf, const float* __restrict__ Wp,
                  const float* __restrict__ bp, const float* __restrict__ Mv0,
                  float* __restrict__ out)
{
    extern __shared__ __align__(16) float smf[];
    float* s_e     = smf + O_E;
    float* s_a     = smf + O_A;
    float* s_w     = smf + O_WW;
    float* s_fk    = smf + O_FK;
    float* s_rp    = smf + O_RP;
    float* s_rf    = smf + O_RF;
    float* s_fp    = smf + O_FP;
    float* s_red   = smf + O_RED;
    int*   s_q     = reinterpret_cast<int*>(smf + O_Q);
    int*   s_qa    = reinterpret_cast<int*>(smf + O_QA);
    float* s_stage = smf + O_STAGE;

    const int b   = blockIdx.x;
    const int tid = threadIdx.x;
    const int u   = tid & 255;
    const int mh  = tid >> 8;      // m-half for phase A
    const int f   = tid & 127;
    const int g   = tid >> 7;      // u-quarter for phase B

    const uint32_t u_e  = s2u(s_e)  + tid * 4;
    const uint32_t u_a  = s2u(s_a)  + tid * 4;
    const uint32_t u_w  = s2u(s_w)  + tid * 4;
    const uint32_t u_fk = s2u(s_fk) + tid * 4;

    for (int idx = tid; idx < SS; idx += 512) {
        s_q [idx] = q [b * SS + idx];
        s_qa[idx] = qa[b * SS + idx];
    }

    // ---- Wf quarter -> registers via coalesced smem bounce ----------------
    ull wfr[32];
    #pragma unroll 1
    for (int c = 0; c < 4; c++) {
        if (c) __syncthreads();
        for (int idx = tid; idx < 32 * VM; idx += 512) {
            const int fr = idx >> 8, uu = idx & 255;
            s_stage[fr * STG + uu] = Wf[(c * 32 + fr) * (KD + VM) + uu];
        }
        __syncthreads();
        if ((f >> 5) == c) {
            const ull* p = reinterpret_cast<const ull*>(s_stage + (f & 31) * STG + g * 64);
            #pragma unroll
            for (int j2 = 0; j2 < 32; j2++) wfr[j2] = p[j2];
        }
    }

    // ---- state: Mv[mh-half, u] as 16 packed pairs -------------------------
    ull mv2[16];
    #pragma unroll
    for (int m2 = 0; m2 < 16; m2++) {
        const int m = mh * 32 + 2 * m2;
        mv2[m2] = pk2(Mv0[m * VM + u], Mv0[(m + 1) * VM + u]);
    }

    const float wp_f = Wp[f];
    const float bp0  = bp[0];
    __syncthreads();

    // ---- span-0 gates into parity-0 buffers (synchronous) -----------------
    if (tid < 256) {
        #pragma unroll
        for (int j = 0; j < TSP; j++) {
            const int qat = s_qa[j];
            s_e[j * VM + tid] = g_etab[qat * VM + tid];
            s_a[j * VM + tid] = g_atab[qat * VM + tid];
        }
    }
    if (tid < MSZ) {
        #pragma unroll
        for (int j = 0; j < TSP; j++)
            s_w[j * MSZ + tid] = g_wtab[s_q[j] * MSZ + tid];
    }
    __syncthreads();

    #pragma unroll 1
    for (int s = 0; s < NSP; s++) {
        const int p  = s & 1;
        const int pn = p ^ 1;

        // ---- cp.async prefetch --------------------------------------------
        {
            const int sn = (s + 1 < NSP) ? s + 1 : s;
            if (tid < 256) {
                #pragma unroll
                for (int j = 0; j < TSP; j++) {
                    const int qan = s_qa[sn * TSP + j];
                    cpa4(u_e + (pn * TSP + j) * VM * 4, g_etab + qan * VM + tid);
                    cpa4(u_a + (pn * TSP + j) * VM * 4, g_atab + qan * VM + tid);
                }
            }
            if (tid < MSZ) {
                #pragma unroll
                for (int j = 0; j < TSP; j++)
                    cpa4(u_w + (pn * TSP + j) * MSZ * 4,
                         g_wtab + s_q[sn * TSP + j] * MSZ + tid);
            }
            if (tid < FD) {
                #pragma unroll
                for (int j = 0; j < TSP; j++)
                    cpa4(u_fk + (p * TSP + j) * FD * 4,
                         g_fktab + s_q[s * TSP + j] * FD + tid);
            }
            CPA_COMMIT();
        }

        // ---- Phase A x4 (half m-range) ------------------------------------
        const float* sep = s_e + p * TSP * VM;
        const float* sap = s_a + p * TSP * VM;
        const float* swp = s_w + p * TSP * MSZ;
        #pragma unroll
        for (int j = 0; j < TSP; j++) {
            const float e_c = sep[j * VM + u];
            const float a_c = sap[j * VM + u];
            const ull ne2 = pk2(-e_c, -e_c);
            const ull a2  = pk2(a_c, a_c);
            ull r0 = 0ull, r1 = 0ull;
            const ulonglong2* sw2 =
                reinterpret_cast<const ulonglong2*>(swp + j * MSZ + mh * 32);
            #pragma unroll
            for (int m4 = 0; m4 < 8; m4++) {
                const ulonglong2 wp = sw2[m4];
                const ull mA = mv2[2 * m4], mB = mv2[2 * m4 + 1];
                r0 = fma2(wp.x, mA, r0);
                r1 = fma2(wp.y, mB, r1);
                const ull tA = fma2(ne2, mA, a2);
                const ull tB = fma2(ne2, mB, a2);
                mv2[2 * m4]     = fma2(wp.x, tA, mA);
                mv2[2 * m4 + 1] = fma2(wp.y, tB, mB);
            }
            float x0, x1, x2, x3;
            upk2(r0, x0, x1); upk2(r1, x2, x3);
            s_rp[j * 512 + mh * 256 + u] = (x0 + x1) + (x2 + x3);
        }

        // ---- Phase E for span s-1 (fk in parity pn buffer) -----------------
        if (s > 0 && tid < FD) {
            const float* fkq = s_fk + pn * TSP * FD;
            #pragma unroll
            for (int j = 0; j < TSP; j++) {
                const float pre = s_fp[j * 512 + f]       + s_fp[j * 512 + 128 + f]
                                + s_fp[j * 512 + 256 + f] + s_fp[j * 512 + 384 + f]
                                + fkq[j * FD + f];
                float term = wp_f * tanhf(pre);
                #pragma unroll
                for (int o = 16; o > 0; o >>= 1)
                    term += __shfl_xor_sync(0xffffffffu, term, o);
                if ((tid & 31) == 0) s_red[j * 4 + (tid >> 5)] = term;
            }
        }
        __syncthreads();                       // s_rp + s_red ready

        // ---- fold r halves (256 threads, float4) + out-store (others) -----
        if (tid < 256) {
            const int j  = tid >> 6, u4 = tid & 63;
            const float4 A  = *reinterpret_cast<const float4*>(s_rp + j * 512 + u4 * 4);
            const float4 Bv = *reinterpret_cast<const float4*>(s_rp + j * 512 + 256 + u4 * 4);
            float4 S;
            S.x = A.x + Bv.x; S.y = A.y + Bv.y; S.z = A.z + Bv.z; S.w = A.w + Bv.w;
            *reinterpret_cast<float4*>(s_rf + j * VM + u4 * 4) = S;
        } else if (s > 0 && tid < 256 + TSP) {
            const int j = tid - 256;
            out[b * SS + (s - 1) * TSP + j] = bp0
                + s_red[j * 4 + 0] + s_red[j * 4 + 1]
                + s_red[j * 4 + 2] + s_red[j * 4 + 3];
        }
        __syncthreads();                       // s_rf ready

        // ---- Phase B x4 (u-quarter) ---------------------------------------
        #pragma unroll
        for (int j = 0; j < TSP; j++) {
            ull acc0 = 0ull, acc1 = 0ull;
            const ulonglong2* sr2 =
                reinterpret_cast<const ulonglong2*>(s_rf + j * VM + g * 64);
            #pragma unroll
            for (int j4 = 0; j4 < 16; j4++) {
                const ulonglong2 rp = sr2[j4];
                acc0 = fma2(wfr[2 * j4],     rp.x, acc0);
                acc1 = fma2(wfr[2 * j4 + 1], rp.y, acc1);
            }
            float y0, y1, y2, y3;
            upk2(acc0, y0, y1); upk2(acc1, y2, y3);
            s_fp[j * 512 + g * 128 + f] = (y0 + y1) + (y2 + y3);
        }

        CPA_WAIT0();
        __syncthreads();                       // span boundary
    }

    // ---- epilogue: E + store for last span --------------------------------
    {
        const int pL = (NSP - 1) & 1;
        if (tid < FD) {
            const float* fkq = s_fk + pL * TSP * FD;
            #pragma unroll
            for (int j = 0; j < TSP; j++) {
                const float pre = s_fp[j * 512 + f]       + s_fp[j * 512 + 128 + f]
                                + s_fp[j * 512 + 256 + f] + s_fp[j * 512 + 384 + f]
                                + fkq[j * FD + f];
                float term = wp_f * tanhf(pre);
                #pragma unroll
                for (int o = 16; o > 0; o >>= 1)
                    term += __shfl_xor_sync(0xffffffffu, term, o);
                if ((tid & 31) == 0) s_red[j * 4 + (tid >> 5)] = term;
            }
        }
        __syncthreads();
        if (tid < TSP) {
            out[b * SS + (NSP - 1) * TSP + tid] = bp0
                + s_red[tid * 4 + 0] + s_red[tid * 4 + 1]
                + s_red[tid * 4 + 2] + s_red[tid * 4 + 3];
        }
    }
}

// ---------------------------------------------------------------------------
// Launch. Inputs: q, qa, k_emb, v_emb, Wf, bf, Wp, bp, We, be, Wa, ba, Mk, Mv0
// ---------------------------------------------------------------------------
extern "C" void kernel_launch(void* const* d_in, const int* in_sizes, int n_in,
                              void* d_out, int out_size)
{
    const int*   q     = (const int*)  d_in[0];
    const int*   qa    = (const int*)  d_in[1];
    const float* k_emb = (const float*)d_in[2];
    const float* v_emb = (const float*)d_in[3];
    const float* Wf    = (const float*)d_in[4];
    const float* bf    = (const float*)d_in[5];
    const float* Wp    = (const float*)d_in[6];
    const float* bp    = (const float*)d_in[7];
    const float* We    = (const float*)d_in[8];
    const float* be    = (const float*)d_in[9];
    const float* Wa    = (const float*)d_in[10];
    const float* ba    = (const float*)d_in[11];
    const float* Mk    = (const float*)d_in[12];
    const float* Mv0   = (const float*)d_in[13];
    float* out = (float*)d_out;

    cudaFuncSetAttribute(build_wfk_kernel,
                         cudaFuncAttributeMaxDynamicSharedMemorySize, WFK_SMEM);
    cudaFuncSetAttribute(dkvmn_main_kernel,
                         cudaFuncAttributeMaxDynamicSharedMemorySize, MAIN_SMEM);

    transpose_we_wa<<<dim3(8, 8, 2), dim3(32, 8)>>>(We, Wa);
    build_wfk_kernel<<<(NQ1 + WTI - 1) / WTI, 256, WFK_SMEM>>>(k_emb, Mk, Wf, bf);
    build_ea_kernel<<<(NQA1 + TI - 1) / TI, 256>>>(v_emb, be, ba);
    dkvmn_main_kernel<<<BB, 512, MAIN_SMEM>>>(q, qa, Wf, Wp, bp, Mv0, out);
}

// round 8
// speedup vs baseline: 1.1679x; 1.1679x over previous
#include <cuda_runtime.h>
#include <cstdint>

// Problem dims (fixed by dataset)
#define NQ1   10001
#define NQA1  20001
#define MSZ   64
#define KD    128
#define VD    256
#define VM    256
#define FD    128
#define BB    512
#define SS    512

typedef unsigned long long ull;

// ---------------------------------------------------------------------------
// f32x2 packed-math + cp.async helpers
// ---------------------------------------------------------------------------
__device__ __forceinline__ ull pk2(float a, float b) {
    ull r; asm("mov.b64 %0, {%1, %2};" : "=l"(r) : "f"(a), "f"(b)); return r;
}
__device__ __forceinline__ void upk2(ull p, float& a, float& b) {
    asm("mov.b64 {%0, %1}, %2;" : "=f"(a), "=f"(b) : "l"(p));
}
__device__ __forceinline__ ull fma2(ull a, ull b, ull c) {
    ull d; asm("fma.rn.f32x2 %0, %1, %2, %3;" : "=l"(d) : "l"(a), "l"(b), "l"(c)); return d;
}
__device__ __forceinline__ uint32_t s2u(const void* p) {
    uint32_t a;
    asm("{ .reg .u64 t; cvta.to.shared.u64 t, %1; cvt.u32.u64 %0, t; }" : "=r"(a) : "l"(p));
    return a;
}
__device__ __forceinline__ void cpa4(uint32_t s, const void* g) {
    asm volatile("cp.async.ca.shared.global [%0], [%1], 4;" :: "r"(s), "l"(g));
}
__device__ __forceinline__ void cpa8(uint32_t s, const void* g) {
    asm volatile("cp.async.ca.shared.global [%0], [%1], 8;" :: "r"(s), "l"(g));
}
#define CPA_COMMIT() asm volatile("cp.async.commit_group;" ::: "memory")
#define CPA_WAIT0()  asm volatile("cp.async.wait_group 0;"  ::: "memory")

// ---------------------------------------------------------------------------
// Scratch tables
// ---------------------------------------------------------------------------
__device__ float  g_wtab [NQ1  * MSZ];
__device__ float  g_fktab[NQ1  * FD ];
__device__ float2 g_eatab[NQA1 * VM ];   // interleaved (e, a) : 41 MB
__device__ float  g_WeT  [VD * VM];
__device__ float  g_WaT  [VD * VM];

// ---------------------------------------------------------------------------
// Transpose We/Wa (256x256) into [j][u] layout
// ---------------------------------------------------------------------------
__global__ void transpose_we_wa(const float* __restrict__ We,
                                const float* __restrict__ Wa)
{
    __shared__ float tile[32][33];
    const float* src = blockIdx.z ? Wa : We;
    float* dst = blockIdx.z ? g_WaT : g_WeT;
    const int bx = blockIdx.x * 32;
    const int by = blockIdx.y * 32;
    #pragma unroll
    for (int k = 0; k < 4; k++)
        tile[threadIdx.y + k * 8][threadIdx.x] =
            src[(by + threadIdx.y + k * 8) * VD + bx + threadIdx.x];
    __syncthreads();
    #pragma unroll
    for (int k = 0; k < 4; k++)
        dst[(bx + threadIdx.y + k * 8) * VM + by + threadIdx.x] =
            tile[threadIdx.x][threadIdx.y + k * 8];
}

// ---------------------------------------------------------------------------
// Kernel A: per-q tables (32 indices/block, coalesced + conflict-free)
// ---------------------------------------------------------------------------
#define WTI 32
#define WFK_SMEM ((WTI*KD + MSZ*132 + FD*132 + WTI*MSZ) * 4)

__global__ void __launch_bounds__(256)
build_wfk_kernel(const float* __restrict__ k_emb, const float* __restrict__ Mk,
                 const float* __restrict__ Wf,    const float* __restrict__ bf)
{
    extern __shared__ float sm[];
    float* k_s   = sm;
    float* Mk_s  = sm + WTI * KD;
    float* Wfk_s = Mk_s + MSZ * 132;
    float* sc_s  = Wfk_s + FD * 132;

    const int tid  = threadIdx.x;
    const int base = blockIdx.x * WTI;

    for (int idx = tid; idx < WTI * KD; idx += 256) {
        const int i = idx >> 7, j = idx & 127;
        const int gi = min(base + i, NQ1 - 1);
        k_s[i * KD + j] = k_emb[gi * KD + j];
    }
    for (int idx = tid; idx < MSZ * KD; idx += 256) {
        const int m = idx >> 7, j = idx & 127;
        Mk_s[m * 132 + j] = Mk[idx];
    }
    for (int idx = tid; idx < FD * KD; idx += 256) {
        const int ff = idx >> 7, j = idx & 127;
        Wfk_s[ff * 132 + j] = Wf[ff * (KD + VM) + VM + j];
    }
    __syncthreads();

    {
        const int m = tid & 63, ig = tid >> 6;
        float acc[8];
        #pragma unroll
        for (int ii = 0; ii < 8; ii++) acc[ii] = 0.f;
        #pragma unroll 4
        for (int j4 = 0; j4 < KD / 4; j4++) {
            const float4 mk = *reinterpret_cast<const float4*>(Mk_s + m * 132 + j4 * 4);
            #pragma unroll
            for (int ii = 0; ii < 8; ii++) {
                const float4 kv = *reinterpret_cast<const float4*>(k_s + (ig * 8 + ii) * KD + j4 * 4);
                acc[ii] = fmaf(mk.x, kv.x, fmaf(mk.y, kv.y, fmaf(mk.z, kv.z, fmaf(mk.w, kv.w, acc[ii]))));
            }
        }
        #pragma unroll
        for (int ii = 0; ii < 8; ii++) sc_s[(ig * 8 + ii) * MSZ + m] = acc[ii];
    }
    __syncthreads();

    {
        const int lane = tid & 31, w = tid >> 5;
        #pragma unroll
        for (int rep = 0; rep < 4; rep++) {
            const int i = w + rep * 8;
            const float sa = sc_s[i * MSZ + lane];
            const float sb = sc_s[i * MSZ + 32 + lane];
            float mx = fmaxf(sa, sb);
            #pragma unroll
            for (int o = 16; o > 0; o >>= 1) mx = fmaxf(mx, __shfl_xor_sync(0xffffffffu, mx, o));
            const float ea = expf(sa - mx), eb = expf(sb - mx);
            float s = ea + eb;
            #pragma unroll
            for (int o = 16; o > 0; o >>= 1) s += __shfl_xor_sync(0xffffffffu, s, o);
            const float inv = 1.f / s;
            const int gi = base + i;
            if (gi < NQ1) {
                g_wtab[gi * MSZ + lane]      = ea * inv;
                g_wtab[gi * MSZ + 32 + lane] = eb * inv;
            }
        }
    }

    {
        const int ff = tid & 127, h = tid >> 7;
        float fa[16];
        #pragma unroll
        for (int ii = 0; ii < 16; ii++) fa[ii] = 0.f;
        #pragma unroll 2
        for (int j4 = 0; j4 < KD / 4; j4++) {
            const float4 wv = *reinterpret_cast<const float4*>(Wfk_s + ff * 132 + j4 * 4);
            #pragma unroll
            for (int ii = 0; ii < 16; ii++) {
                const float4 kv = *reinterpret_cast<const float4*>(k_s + (h * 16 + ii) * KD + j4 * 4);
                fa[ii] = fmaf(wv.x, kv.x, fmaf(wv.y, kv.y, fmaf(wv.z, kv.z, fmaf(wv.w, kv.w, fa[ii]))));
            }
        }
        const float bff = bf[ff];
        #pragma unroll
        for (int ii = 0; ii < 16; ii++) {
            const int gi = base + h * 16 + ii;
            if (gi < NQ1) g_fktab[gi * FD + ff] = fa[ii] + bff;
        }
    }
}

// ---------------------------------------------------------------------------
// Kernel B: per-qa tables from transposed weights -> interleaved float2
// ---------------------------------------------------------------------------
#define TI 32
__global__ void __launch_bounds__(256)
build_ea_kernel(const float* __restrict__ v_emb,
                const float* __restrict__ be, const float* __restrict__ ba)
{
    __shared__ float4 v_s[TI * (VD / 4)];
    const int tid  = threadIdx.x;
    const int base = blockIdx.x * TI;

    for (int idx = tid; idx < TI * (VD / 4); idx += 256) {
        const int i = idx >> 6, j4 = idx & 63;
        const int gi = min(base + i, NQA1 - 1);
        v_s[i * (VD / 4) + j4] = reinterpret_cast<const float4*>(v_emb)[gi * (VD / 4) + j4];
    }
    __syncthreads();

    const int u = tid;
    float acce[TI], acca[TI];
    #pragma unroll
    for (int i = 0; i < TI; i++) { acce[i] = 0.f; acca[i] = 0.f; }

    #pragma unroll 1
    for (int j4 = 0; j4 < VD / 4; j4++) {
        const int j = j4 * 4;
        const float we0 = g_WeT[(j + 0) * VM + u];
        const float we1 = g_WeT[(j + 1) * VM + u];
        const float we2 = g_WeT[(j + 2) * VM + u];
        const float we3 = g_WeT[(j + 3) * VM + u];
        const float wa0 = g_WaT[(j + 0) * VM + u];
        const float wa1 = g_WaT[(j + 1) * VM + u];
        const float wa2 = g_WaT[(j + 2) * VM + u];
        const float wa3 = g_WaT[(j + 3) * VM + u];
        #pragma unroll
        for (int i = 0; i < TI; i++) {
            const float4 v = v_s[i * (VD / 4) + j4];
            acce[i] = fmaf(we0, v.x, fmaf(we1, v.y, fmaf(we2, v.z, fmaf(we3, v.w, acce[i]))));
            acca[i] = fmaf(wa0, v.x, fmaf(wa1, v.y, fmaf(wa2, v.z, fmaf(wa3, v.w, acca[i]))));
        }
    }

    const float bei = be[u], bai = ba[u];
    #pragma unroll
    for (int i = 0; i < TI; i++) {
        const int gi = base + i;
        if (gi < NQA1) {
            g_eatab[gi * VM + u] = make_float2(
                1.f / (1.f + expf(-(acce[i] + bei))),
                tanhf(acca[i] + bai));
        }
    }
}

// ---------------------------------------------------------------------------
// Main kernel: 512 threads, TSP=8 steps/span, 3 barriers/span (0.375/step).
//   Phase A: thread (u, mh) owns Mv[mh*32..+32, u] in 16 packed regs
//   Phase B: thread (f, g)  owns Wf[f, g*64..+64]  in 32 packed regs
//   Phase E: thread (f, g)  handles steps j=g, j=g+4 (parallel across warps)
// ---------------------------------------------------------------------------
#define TSP 8
#define NSP (SS / TSP)
#define STG 258

// smem layout (floats)
#define O_EA    0                               // [2][TSP][256] float2
#define O_WW    (O_EA + 2 * TSP * VM * 2)       // [2][TSP][64]
#define O_FK    (O_WW + 2 * TSP * MSZ)          // [2][TSP][128]
#define O_RP    (O_FK + 2 * TSP * FD)           // [TSP][512]
#define O_RF    (O_RP + TSP * 512)              // [TSP][256]
#define O_FP    (O_RF + TSP * VM)               // [TSP][512]
#define O_RED   (O_FP + TSP * 512)              // [TSP*4]
#define O_Q     (O_RED + TSP * 4)               // [512] int
#define O_QA    (O_Q + SS)
#define O_STAGE (O_QA + SS)                     // 32*258
#define MAIN_SMEM ((O_STAGE + 32 * STG) * 4)

__global__ void __launch_bounds__(512, 1)
dkvmn_main_kernel(const int* __restrict__ q,  const int* __restrict__ qa,
                  const float* __restrict__ Wf, const float* __restrict__ Wp,
                  const float* __restrict__ bp, const float* __restrict__ Mv0,
                  float* __restrict__ out)
{
    extern __shared__ __align__(16) float smf[];
    float2* s_ea   = reinterpret_cast<float2*>(smf + O_EA);
    float*  s_w    = smf + O_WW;
    float*  s_fk   = smf + O_FK;
    float*  s_rp   = smf + O_RP;
    float*  s_rf   = smf + O_RF;
    float*  s_fp   = smf + O_FP;
    float*  s_red  = smf + O_RED;
    int*    s_q    = reinterpret_cast<int*>(smf + O_Q);
    int*    s_qa   = reinterpret_cast<int*>(smf + O_QA);
    float*  s_stage = smf + O_STAGE;

    const int b   = blockIdx.x;
    const int tid = threadIdx.x;
    const int u   = tid & 255;
    const int mh  = tid >> 8;      // m-half for phase A
    const int f   = tid & 127;
    const int g   = tid >> 7;      // u-quarter for phase B / step-group for E

    const uint32_t u_ea = s2u(s_ea) + tid * 8;
    const uint32_t u_w  = s2u(s_w)  + tid * 4;
    const uint32_t u_fk = s2u(s_fk) + tid * 4;

    for (int idx = tid; idx < SS; idx += 512) {
        s_q [idx] = q [b * SS + idx];
        s_qa[idx] = qa[b * SS + idx];
    }

    // ---- Wf quarter -> registers via coalesced smem bounce ----------------
    ull wfr[32];
    #pragma unroll 1
    for (int c = 0; c < 4; c++) {
        if (c) __syncthreads();
        for (int idx = tid; idx < 32 * VM; idx += 512) {
            const int fr = idx >> 8, uu = idx & 255;
            s_stage[fr * STG + uu] = Wf[(c * 32 + fr) * (KD + VM) + uu];
        }
        __syncthreads();
        if ((f >> 5) == c) {
            const ull* p = reinterpret_cast<const ull*>(s_stage + (f & 31) * STG + g * 64);
            #pragma unroll
            for (int j2 = 0; j2 < 32; j2++) wfr[j2] = p[j2];
        }
    }

    // ---- state: Mv[mh-half, u] as 16 packed pairs -------------------------
    ull mv2[16];
    #pragma unroll
    for (int m2 = 0; m2 < 16; m2++) {
        const int m = mh * 32 + 2 * m2;
        mv2[m2] = pk2(Mv0[m * VM + u], Mv0[(m + 1) * VM + u]);
    }

    const float wp_f = Wp[f];
    const float bp0  = bp[0];
    __syncthreads();

    // ---- span-0 gates into parity-0 buffers (synchronous) -----------------
    if (tid < 256) {
        #pragma unroll
        for (int j = 0; j < TSP; j++)
            s_ea[j * VM + tid] = g_eatab[s_qa[j] * VM + tid];
    }
    if (tid < MSZ) {
        #pragma unroll
        for (int j = 0; j < TSP; j++)
            s_w[j * MSZ + tid] = g_wtab[s_q[j] * MSZ + tid];
    }
    __syncthreads();

    #pragma unroll 1
    for (int s = 0; s < NSP; s++) {
        const int p  = s & 1;
        const int pn = p ^ 1;

        // ---- cp.async prefetch --------------------------------------------
        {
            const int sn = (s + 1 < NSP) ? s + 1 : s;
            if (tid < 256) {
                #pragma unroll
                for (int j = 0; j < TSP; j++)
                    cpa8(u_ea + (pn * TSP + j) * VM * 8,
                         g_eatab + s_qa[sn * TSP + j] * VM + tid);
            }
            if (tid < MSZ) {
                #pragma unroll
                for (int j = 0; j < TSP; j++)
                    cpa4(u_w + (pn * TSP + j) * MSZ * 4,
                         g_wtab + s_q[sn * TSP + j] * MSZ + tid);
            }
            if (tid < FD) {
                #pragma unroll
                for (int j = 0; j < TSP; j++)
                    cpa4(u_fk + (p * TSP + j) * FD * 4,
                         g_fktab + s_q[s * TSP + j] * FD + tid);
            }
            CPA_COMMIT();
        }

        // ---- Phase A x8 (half m-range) ------------------------------------
        const float2* seap = s_ea + p * TSP * VM;
        const float*  swp  = s_w  + p * TSP * MSZ;
        #pragma unroll
        for (int j = 0; j < TSP; j++) {
            const float2 ea = seap[j * VM + u];
            const ull ne2 = pk2(-ea.x, -ea.x);
            const ull a2  = pk2(ea.y, ea.y);
            ull r0 = 0ull, r1 = 0ull;
            const ulonglong2* sw2 =
                reinterpret_cast<const ulonglong2*>(swp + j * MSZ + mh * 32);
            #pragma unroll
            for (int m4 = 0; m4 < 8; m4++) {
                const ulonglong2 wp = sw2[m4];
                const ull mA = mv2[2 * m4], mB = mv2[2 * m4 + 1];
                r0 = fma2(wp.x, mA, r0);
                r1 = fma2(wp.y, mB, r1);
                const ull tA = fma2(ne2, mA, a2);
                const ull tB = fma2(ne2, mB, a2);
                mv2[2 * m4]     = fma2(wp.x, tA, mA);
                mv2[2 * m4 + 1] = fma2(wp.y, tB, mB);
            }
            float x0, x1, x2, x3;
            upk2(r0, x0, x1); upk2(r1, x2, x3);
            s_rp[j * 512 + mh * 256 + u] = (x0 + x1) + (x2 + x3);
        }

        // ---- Phase E for span s-1: thread (f,g) handles j = g, g+4 --------
        if (s > 0) {
            const float* fkq = s_fk + pn * TSP * FD;
            #pragma unroll
            for (int jj = 0; jj < 2; jj++) {
                const int j = g + jj * 4;
                const float pre = s_fp[j * 512 + f]       + s_fp[j * 512 + 128 + f]
                                + s_fp[j * 512 + 256 + f] + s_fp[j * 512 + 384 + f]
                                + fkq[j * FD + f];
                float term = wp_f * tanhf(pre);
                #pragma unroll
                for (int o = 16; o > 0; o >>= 1)
                    term += __shfl_xor_sync(0xffffffffu, term, o);
                if ((tid & 31) == 0) s_red[j * 4 + (f >> 5)] = term;
            }
        }
        __syncthreads();                       // s_rp + s_red ready

        // ---- fold r halves (all 512 threads) + out-store ------------------
        {
            const int j  = tid >> 6, u4 = tid & 63;
            const float4 A  = *reinterpret_cast<const float4*>(s_rp + j * 512 + u4 * 4);
            const float4 Bv = *reinterpret_cast<const float4*>(s_rp + j * 512 + 256 + u4 * 4);
            float4 S;
            S.x = A.x + Bv.x; S.y = A.y + Bv.y; S.z = A.z + Bv.z; S.w = A.w + Bv.w;
            *reinterpret_cast<float4*>(s_rf + j * VM + u4 * 4) = S;
        }
        if (s > 0 && tid < TSP) {
            out[b * SS + (s - 1) * TSP + tid] = bp0
                + s_red[tid * 4 + 0] + s_red[tid * 4 + 1]
                + s_red[tid * 4 + 2] + s_red[tid * 4 + 3];
        }
        __syncthreads();                       // s_rf ready

        // ---- Phase B x8 (u-quarter) ---------------------------------------
        #pragma unroll
        for (int j = 0; j < TSP; j++) {
            ull acc0 = 0ull, acc1 = 0ull;
            const ulonglong2* sr2 =
                reinterpret_cast<const ulonglong2*>(s_rf + j * VM + g * 64);
            #pragma unroll
            for (int j4 = 0; j4 < 16; j4++) {
                const ulonglong2 rp = sr2[j4];
                acc0 = fma2(wfr[2 * j4],     rp.x, acc0);
                acc1 = fma2(wfr[2 * j4 + 1], rp.y, acc1);
            }
            float y0, y1, y2, y3;
            upk2(acc0, y0, y1); upk2(acc1, y2, y3);
            s_fp[j * 512 + g * 128 + f] = (y0 + y1) + (y2 + y3);
        }

        CPA_WAIT0();
        __syncthreads();                       // span boundary
    }

    // ---- epilogue: E + store for last span --------------------------------
    {
        const int pL = (NSP - 1) & 1;
        const float* fkq = s_fk + pL * TSP * FD;
        #pragma unroll
        for (int jj = 0; jj < 2; jj++) {
            const int j = g + jj * 4;
            const float pre = s_fp[j * 512 + f]       + s_fp[j * 512 + 128 + f]
                            + s_fp[j * 512 + 256 + f] + s_fp[j * 512 + 384 + f]
                            + fkq[j * FD + f];
            float term = wp_f * tanhf(pre);
            #pragma unroll
            for (int o = 16; o > 0; o >>= 1)
                term += __shfl_xor_sync(0xffffffffu, term, o);
            if ((tid & 31) == 0) s_red[j * 4 + (f >> 5)] = term;
        }
        __syncthreads();
        if (tid < TSP) {
            out[b * SS + (NSP - 1) * TSP + tid] = bp0
                + s_red[tid * 4 + 0] + s_red[tid * 4 + 1]
                + s_red[tid * 4 + 2] + s_red[tid * 4 + 3];
        }
    }
}

// ---------------------------------------------------------------------------
// Launch. Inputs: q, qa, k_emb, v_emb, Wf, bf, Wp, bp, We, be, Wa, ba, Mk, Mv0
// ---------------------------------------------------------------------------
extern "C" void kernel_launch(void* const* d_in, const int* in_sizes, int n_in,
                              void* d_out, int out_size)
{
    const int*   q     = (const int*)  d_in[0];
    const int*   qa    = (const int*)  d_in[1];
    const float* k_emb = (const float*)d_in[2];
    const float* v_emb = (const float*)d_in[3];
    const float* Wf    = (const float*)d_in[4];
    const float* bf    = (const float*)d_in[5];
    const float* Wp    = (const float*)d_in[6];
    const float* bp    = (const float*)d_in[7];
    const float* We    = (const float*)d_in[8];
    const float* be    = (const float*)d_in[9];
    const float* Wa    = (const float*)d_in[10];
    const float* ba    = (const float*)d_in[11];
    const float* Mk    = (const float*)d_in[12];
    const float* Mv0   = (const float*)d_in[13];
    float* out = (float*)d_out;

    cudaFuncSetAttribute(build_wfk_kernel,
                         cudaFuncAttributeMaxDynamicSharedMemorySize, WFK_SMEM);
    cudaFuncSetAttribute(dkvmn_main_kernel,
                         cudaFuncAttributeMaxDynamicSharedMemorySize, MAIN_SMEM);

    transpose_we_wa<<<dim3(8, 8, 2), dim3(32, 8)>>>(We, Wa);
    build_wfk_kernel<<<(NQ1 + WTI - 1) / WTI, 256, WFK_SMEM>>>(k_emb, Mk, Wf, bf);
    build_ea_kernel<<<(NQA1 + TI - 1) / TI, 256>>>(v_emb, be, ba);
    dkvmn_main_kernel<<<BB, 512, MAIN_SMEM>>>(q, qa, Wf, Wp, bp, Mv0, out);
}